// round 8
// baseline (speedup 1.0000x reference)
#include <cuda_runtime.h>
#include <stdint.h>

// Problem constants (fixed shapes per setup_inputs)
#define BATCH 4
#define NPTS  2048
#define NB    (BATCH * NPTS)        // 8192 (b,n) pairs
#define GRID_DIM 64                 // coords in [0,64)
#define BITMAP_WORDS (GRID_DIM * GRID_DIM * GRID_DIM / 32)  // 8192 words / batch
#define PRIOR_VOX 4096              // 16^3
#define OCC_K 26
#define OCC_BASE ((size_t)NB * PRIOR_VOX)   // 33,554,432

// Scratch (static __device__ per harness rules):
__device__ unsigned int g_bitmap[BATCH * BITMAP_WORDS];  // 128 KB occupancy bits
__device__ unsigned int g_ready;   // builder completion count (0..4), reset each replay
__device__ unsigned int g_done;    // CTA completion count, reset each replay

// 26 neighbor offsets; first 6 are the face offsets (order matches reference).
__constant__ int8_t c_noff[26][3] = {
    {-1,0,0},{1,0,0},{0,-1,0},{0,1,0},{0,0,-1},{0,0,1},
    {-1,-1,0},{-1,1,0},{1,-1,0},{1,1,0},
    {-1,0,-1},{-1,0,1},{1,0,-1},{1,0,1},
    {0,-1,-1},{0,-1,1},{0,1,-1},{0,1,1},
    {-1,-1,-1},{-1,-1,1},{-1,1,-1},{-1,1,1},
    {1,-1,-1},{1,-1,1},{1,1,-1},{1,1,1}};

// Single fused kernel. Blocks 0..3 (wave-1 resident by dispatch order, distinct
// SMs) zero+build the per-batch bitmap and release g_ready. Every CTA spins on
// g_ready==4 (wave-2+ CTAs pass immediately), then probes its 26 neighbors
// (warp 0), writes occ, and streams its 4096-float prior tile as 4 fully
// contiguous warp-wide float4 stores per thread. Last CTA resets the flags so
// the kernel is graph-replay deterministic.
__global__ __launch_bounds__(256, 8)
void fused_kernel(const int* __restrict__ coords, float* __restrict__ out) {
    const int bn = blockIdx.x;
    const int b  = bn >> 11;
    const int t  = threadIdx.x;

    // ---- Build phase: blocks 0..3 each own one batch's bitmap ----
    if (bn < BATCH) {
        unsigned int* bm = g_bitmap + bn * BITMAP_WORDS;
        const uint4 z4 = make_uint4(0u, 0u, 0u, 0u);
        #pragma unroll
        for (int i = 0; i < BITMAP_WORDS / 4 / 256; i++)        // 8 x STG.128
            reinterpret_cast<uint4*>(bm)[t + i * 256] = z4;
        __syncthreads();
        const int* c = coords + bn * NPTS * 3;
        #pragma unroll
        for (int i = 0; i < NPTS / 256; i++) {                  // 8 atomics
            int n = t + i * 256;
            int x = c[n * 3 + 0];
            int y = c[n * 3 + 1];
            int z = c[n * 3 + 2];
            int idx = (x << 12) | (y << 6) | z;                 // x*4096+y*64+z
            atomicOr(&bm[idx >> 5], 1u << (idx & 31));
        }
        __threadfence();        // publish bitmap (release)
        __syncthreads();
        if (t == 0) atomicAdd(&g_ready, 1u);
    }

    // ---- Wait for all 4 bitmaps ----
    if (t == 0) {
        while (atomicAdd(&g_ready, 0u) < BATCH) __nanosleep(64);
    }
    __syncthreads();            // block-wide acquire of the flag observation

    // ---- Probe: warp 0 lanes 0..25, one bitmap load each ----
    __shared__ unsigned s_mask;
    if (t < 32) {
        const int x = coords[bn * 3 + 0];
        const int y = coords[bn * 3 + 1];
        const int z = coords[bn * 3 + 2];
        bool present = false;
        if (t < OCC_K) {
            int nx = x + c_noff[t][0];
            int ny = y + c_noff[t][1];
            int nz = z + c_noff[t][2];
            if ((unsigned)nx < GRID_DIM && (unsigned)ny < GRID_DIM &&
                (unsigned)nz < GRID_DIM) {
                int idx = (nx << 12) | (ny << 6) | nz;
                unsigned w = __ldcg(&g_bitmap[b * BITMAP_WORDS + (idx >> 5)]);
                present = (w >> (idx & 31)) & 1u;
            }
            out[OCC_BASE + (size_t)bn * OCC_K + t] = present ? 1.0f : 0.0f;
        }
        unsigned bal = __ballot_sync(0xffffffffu, present);
        if (t == 0) s_mask = bal;
    }
    __syncthreads();

    // ---- Prior store stream ----
    const unsigned m = s_mask;
    const float r15 = 1.0f / 15.0f;
    float* out_p = out + (size_t)bn * PRIOR_VOX;

    // v = t*4 + q*1024; i = (t>>6) + 4q, j = (t>>2)&15, k0 = (t&3)*4.
    // y- and z-face mins are invariant across the 4 q iterations.
    const float gy = (float)((t >> 2) & 15) * r15;
    const int   k0 = (t & 3) << 2;
    const int   i0 = t >> 6;

    float ybase = 1.0f;
    if (!(m & 4u))  ybase = fminf(ybase, gy);
    if (!(m & 8u))  ybase = fminf(ybase, 1.0f - gy);

    float yz[4];
    #pragma unroll
    for (int kk = 0; kk < 4; kk++) {
        float gz = (float)(k0 + kk) * r15;
        float v = ybase;
        if (!(m & 16u)) v = fminf(v, gz);
        if (!(m & 32u)) v = fminf(v, 1.0f - gz);
        yz[kk] = v;
    }

    #pragma unroll
    for (int q = 0; q < 4; q++) {
        float gx = (float)(i0 + 4 * q) * r15;   // exact: matches linspace rounding
        float xv = 1.0f;
        if (!(m & 1u)) xv = fminf(xv, gx);
        if (!(m & 2u)) xv = fminf(xv, 1.0f - gx);
        float4 r;
        r.x = fminf(yz[0], xv);
        r.y = fminf(yz[1], xv);
        r.z = fminf(yz[2], xv);
        r.w = fminf(yz[3], xv);
        *reinterpret_cast<float4*>(out_p + (t << 2) + (q << 10)) = r;
    }

    // ---- Last CTA resets the flags for the next graph replay ----
    if (t == 0) {
        unsigned ticket = atomicAdd(&g_done, 1u);
        if (ticket == NB - 1) {
            g_ready = 0u;
            g_done  = 0u;
        }
    }
}

extern "C" void kernel_launch(void* const* d_in, const int* in_sizes, int n_in,
                              void* d_out, int out_size) {
    const int* coords = (const int*)d_in[0];
    float* out = (float*)d_out;

    fused_kernel<<<NB, 256>>>(coords, out);
}